// round 1
// baseline (speedup 1.0000x reference)
#include <cuda_runtime.h>
#include <cstddef>

#define SEQ    4096
#define HID    2048
#define HEADS  16
#define HD     128
#define NB     64
#define BLK    64
#define SCALE  0.08838834764831845f   // 1/sqrt(128)

// ---------------- scratch (static device globals; no allocation allowed) ----
__device__ float g_q[SEQ * HID];
__device__ float g_k[SEQ * HID];
__device__ float g_v[SEQ * HID];
__device__ float g_attn[SEQ * HID];

// ---------------- SGEMM: C[M,N] = A[M,K] * B[N,K]^T  (both row-major) ------
#define BM 128
#define BN 128
#define BKK 8

__global__ __launch_bounds__(256, 2) void sgemm_nt(
    const float* __restrict__ A, const float* __restrict__ B,
    float* __restrict__ C, int M, int N, int K)
{
    __shared__ float As[BKK][BM];
    __shared__ float Bs[BKK][BN];

    const int tid  = threadIdx.x;
    const int bm   = blockIdx.y * BM;
    const int bn   = blockIdx.x * BN;
    const int lrow = tid >> 1;           // 0..127
    const int lseg = (tid & 1) << 2;     // 0 or 4
    const int tx   = tid & 15;
    const int ty   = tid >> 4;

    const float* Ag = A + (size_t)(bm + lrow) * K + lseg;
    const float* Bg = B + (size_t)(bn + lrow) * K + lseg;

    float acc[8][8];
#pragma unroll
    for (int i = 0; i < 8; i++)
#pragma unroll
        for (int j = 0; j < 8; j++) acc[i][j] = 0.f;

    for (int k0 = 0; k0 < K; k0 += BKK) {
        float4 a = *reinterpret_cast<const float4*>(Ag + k0);
        float4 b = *reinterpret_cast<const float4*>(Bg + k0);
        As[lseg + 0][lrow] = a.x; As[lseg + 1][lrow] = a.y;
        As[lseg + 2][lrow] = a.z; As[lseg + 3][lrow] = a.w;
        Bs[lseg + 0][lrow] = b.x; Bs[lseg + 1][lrow] = b.y;
        Bs[lseg + 2][lrow] = b.z; Bs[lseg + 3][lrow] = b.w;
        __syncthreads();

#pragma unroll
        for (int kk = 0; kk < BKK; ++kk) {
            float4 a0 = *reinterpret_cast<const float4*>(&As[kk][ty * 8]);
            float4 a1 = *reinterpret_cast<const float4*>(&As[kk][ty * 8 + 4]);
            float4 b0 = *reinterpret_cast<const float4*>(&Bs[kk][tx * 8]);
            float4 b1 = *reinterpret_cast<const float4*>(&Bs[kk][tx * 8 + 4]);
            float ar[8] = {a0.x, a0.y, a0.z, a0.w, a1.x, a1.y, a1.z, a1.w};
            float br[8] = {b0.x, b0.y, b0.z, b0.w, b1.x, b1.y, b1.z, b1.w};
#pragma unroll
            for (int i = 0; i < 8; i++)
#pragma unroll
                for (int j = 0; j < 8; j++)
                    acc[i][j] = fmaf(ar[i], br[j], acc[i][j]);
        }
        __syncthreads();
    }

    float* Cg = C + (size_t)(bm + ty * 8) * N + bn + tx * 8;
#pragma unroll
    for (int i = 0; i < 8; i++) {
        float4 c0 = {acc[i][0], acc[i][1], acc[i][2], acc[i][3]};
        float4 c1 = {acc[i][4], acc[i][5], acc[i][6], acc[i][7]};
        *reinterpret_cast<float4*>(Cg + (size_t)i * N)     = c0;
        *reinterpret_cast<float4*>(Cg + (size_t)i * N + 4) = c1;
    }
}

// ---------------- block-sparse attention ------------------------------------
// One CTA per (q-block, head). Q tile resident; K then V share one smem
// buffer; online softmax (flash style); 16x16 thread grid.
#define QSTRIDE 132   // 128 + 4 pad: kills LDS bank conflicts on row-major dots

__global__ __launch_bounds__(256) void attn_sparse(
    const float* __restrict__ Q, const float* __restrict__ K,
    const float* __restrict__ V, const int* __restrict__ rand_idx,
    float* __restrict__ O)
{
    extern __shared__ float smem[];
    float* Qs  = smem;                    // 64 * 132
    float* KVs = Qs + 64 * QSTRIDE;       // 64 * 132 (K, then reused for V)
    float* Ssm = KVs + 64 * QSTRIDE;      // 64 * 65
    float* msm = Ssm + 64 * 65;           // 64
    float* lsm = msm + 64;                // 64
    float* csm = lsm + 64;                // 64
    __shared__ int blist[8];
    __shared__ int nblk;

    const int tid = threadIdx.x;
    const int qb  = blockIdx.x;
    const int h   = blockIdx.y;

    if (tid == 0) {
        int cand[6];
        cand[0] = qb; cand[1] = qb - 1; cand[2] = qb + 1;
        cand[3] = 0;  cand[4] = NB - 1; cand[5] = rand_idx[qb];   // N_RANDOM=1
        int cnt = 0;
        for (int c = 0; c < 6; c++) {
            int b = cand[c];
            if (b < 0 || b >= NB) continue;
            bool dup = false;
            for (int d = 0; d < cnt; d++) if (blist[d] == b) dup = true;
            if (!dup) blist[cnt++] = b;
        }
        nblk = cnt;
    }
    if (tid < 64) { msm[tid] = -1e30f; lsm[tid] = 0.f; }

    // load Q tile (64 x 128)
    const float* Qg = Q + (size_t)(qb * BLK) * HID + h * HD;
    for (int i = tid; i < 64 * 32; i += 256) {
        int r = i >> 5, c4 = (i & 31) << 2;
        *reinterpret_cast<float4*>(Qs + r * QSTRIDE + c4) =
            *reinterpret_cast<const float4*>(Qg + (size_t)r * HID + c4);
    }
    __syncthreads();

    const int tx = tid & 15, ty = tid >> 4;
    const int r0 = ty * 4;      // query rows owned by this thread
    const int cS0 = tx * 4;     // S columns owned (for QK^T)
    const int cO0 = tx * 8;     // O columns owned (for PV)
    float oacc[4][8];
#pragma unroll
    for (int i = 0; i < 4; i++)
#pragma unroll
        for (int c = 0; c < 8; c++) oacc[i][c] = 0.f;

    for (int bi = 0; bi < nblk; bi++) {
        const int j = blist[bi];

        // load K block j
        const float* Kg = K + (size_t)(j * BLK) * HID + h * HD;
        for (int i = tid; i < 64 * 32; i += 256) {
            int r = i >> 5, c4 = (i & 31) << 2;
            *reinterpret_cast<float4*>(KVs + r * QSTRIDE + c4) =
                *reinterpret_cast<const float4*>(Kg + (size_t)r * HID + c4);
        }
        __syncthreads();

        // S = Q K^T * scale  (each thread: 4x4 tile)
        float s[4][4];
#pragma unroll
        for (int i = 0; i < 4; i++)
#pragma unroll
            for (int jj = 0; jj < 4; jj++) s[i][jj] = 0.f;

        for (int k = 0; k < HD; k += 4) {
            float4 q4[4], k4[4];
#pragma unroll
            for (int i = 0; i < 4; i++)
                q4[i] = *reinterpret_cast<const float4*>(Qs + (r0 + i) * QSTRIDE + k);
#pragma unroll
            for (int jj = 0; jj < 4; jj++)
                k4[jj] = *reinterpret_cast<const float4*>(KVs + (cS0 + jj) * QSTRIDE + k);
#pragma unroll
            for (int i = 0; i < 4; i++)
#pragma unroll
                for (int jj = 0; jj < 4; jj++)
                    s[i][jj] += q4[i].x * k4[jj].x + q4[i].y * k4[jj].y +
                                q4[i].z * k4[jj].z + q4[i].w * k4[jj].w;
        }
#pragma unroll
        for (int i = 0; i < 4; i++)
#pragma unroll
            for (int jj = 0; jj < 4; jj++)
                Ssm[(r0 + i) * 65 + cS0 + jj] = s[i][jj] * SCALE;
        __syncthreads();

        // load V block j (reuses KVs; K no longer needed) while 64 threads
        // do the row softmax update on Ssm
        const float* Vg = V + (size_t)(j * BLK) * HID + h * HD;
        for (int i = tid; i < 64 * 32; i += 256) {
            int r = i >> 5, c4 = (i & 31) << 2;
            *reinterpret_cast<float4*>(KVs + r * QSTRIDE + c4) =
                *reinterpret_cast<const float4*>(Vg + (size_t)r * HID + c4);
        }
        if (tid < 64) {
            float* srow = Ssm + tid * 65;
            float m_old = msm[tid];
            float mx = m_old;
            for (int c = 0; c < 64; c++) mx = fmaxf(mx, srow[c]);
            float corr = __expf(m_old - mx);
            float sum = 0.f;
            for (int c = 0; c < 64; c++) {
                float e = __expf(srow[c] - mx);
                srow[c] = e;
                sum += e;
            }
            lsm[tid] = lsm[tid] * corr + sum;
            msm[tid] = mx;
            csm[tid] = corr;
        }
        __syncthreads();

        // rescale accumulators, then O += P * V
        float cr[4];
#pragma unroll
        for (int i = 0; i < 4; i++) {
            cr[i] = csm[r0 + i];
#pragma unroll
            for (int c = 0; c < 8; c++) oacc[i][c] *= cr[i];
        }
#pragma unroll 4
        for (int kk = 0; kk < 64; kk++) {
            float4 v0 = *reinterpret_cast<const float4*>(KVs + kk * QSTRIDE + cO0);
            float4 v1 = *reinterpret_cast<const float4*>(KVs + kk * QSTRIDE + cO0 + 4);
            float p[4];
#pragma unroll
            for (int i = 0; i < 4; i++) p[i] = Ssm[(r0 + i) * 65 + kk];
#pragma unroll
            for (int i = 0; i < 4; i++) {
                oacc[i][0] = fmaf(p[i], v0.x, oacc[i][0]);
                oacc[i][1] = fmaf(p[i], v0.y, oacc[i][1]);
                oacc[i][2] = fmaf(p[i], v0.z, oacc[i][2]);
                oacc[i][3] = fmaf(p[i], v0.w, oacc[i][3]);
                oacc[i][4] = fmaf(p[i], v1.x, oacc[i][4]);
                oacc[i][5] = fmaf(p[i], v1.y, oacc[i][5]);
                oacc[i][6] = fmaf(p[i], v1.z, oacc[i][6]);
                oacc[i][7] = fmaf(p[i], v1.w, oacc[i][7]);
            }
        }
        __syncthreads();
    }

    // epilogue: O /= l, write head-interleaved [S, HID] so Wo GEMM is direct
    float* Og = O + (size_t)(qb * BLK) * HID + h * HD;
#pragma unroll
    for (int i = 0; i < 4; i++) {
        float inv = 1.f / lsm[r0 + i];
        float4 o0 = {oacc[i][0] * inv, oacc[i][1] * inv, oacc[i][2] * inv, oacc[i][3] * inv};
        float4 o1 = {oacc[i][4] * inv, oacc[i][5] * inv, oacc[i][6] * inv, oacc[i][7] * inv};
        *reinterpret_cast<float4*>(Og + (size_t)(r0 + i) * HID + cO0)     = o0;
        *reinterpret_cast<float4*>(Og + (size_t)(r0 + i) * HID + cO0 + 4) = o1;
    }
}

// ---------------- launch -----------------------------------------------------
#define ATTN_SMEM_BYTES ((64 * QSTRIDE * 2 + 64 * 65 + 3 * 64) * (int)sizeof(float))

extern "C" void kernel_launch(void* const* d_in, const int* in_sizes, int n_in,
                              void* d_out, int out_size)
{
    const float* x    = (const float*)d_in[0];  // hidden_states [1,4096,2048]
    const int*   ridx = (const int*)d_in[1];    // rand_idx [64,1]
    const float* Wq   = (const float*)d_in[2];
    const float* Wk   = (const float*)d_in[3];
    const float* Wv   = (const float*)d_in[4];
    const float* Wo   = (const float*)d_in[5];
    float* out = (float*)d_out;

    float *q, *k, *v, *attn;
    cudaGetSymbolAddress((void**)&q,    g_q);
    cudaGetSymbolAddress((void**)&k,    g_k);
    cudaGetSymbolAddress((void**)&v,    g_v);
    cudaGetSymbolAddress((void**)&attn, g_attn);

    cudaFuncSetAttribute(attn_sparse,
                         cudaFuncAttributeMaxDynamicSharedMemorySize,
                         ATTN_SMEM_BYTES);

    dim3 ggrid(HID / BN, SEQ / BM);   // (16, 32)
    sgemm_nt<<<ggrid, 256>>>(x, Wq, q, SEQ, HID, HID);
    sgemm_nt<<<ggrid, 256>>>(x, Wk, k, SEQ, HID, HID);
    sgemm_nt<<<ggrid, 256>>>(x, Wv, v, SEQ, HID, HID);

    attn_sparse<<<dim3(NB, HEADS), 256, ATTN_SMEM_BYTES>>>(q, k, v, ridx, attn);

    sgemm_nt<<<ggrid, 256>>>(attn, Wo, out, SEQ, HID, HID);
}

// round 3
// speedup vs baseline: 1.9118x; 1.9118x over previous
#include <cuda_runtime.h>
#include <cuda_bf16.h>
#include <cstdint>
#include <cstddef>

#define SEQ    4096
#define HID    2048
#define HEADS  16
#define HD     128
#define NB     64
#define BLK    64
#define SCALE  0.08838834764831845f   // 1/sqrt(128)

#define GM 4096
#define GN 2048
#define GK 2048

// ---------------- scratch (static device globals; no allocation allowed) ----
__device__ float g_q[SEQ * HID];
__device__ float g_k[SEQ * HID];
__device__ float g_v[SEQ * HID];
__device__ float g_attn[SEQ * HID];
__device__ __nv_bfloat16 g_ah[SEQ * HID];   // activation hi plane
__device__ __nv_bfloat16 g_al[SEQ * HID];   // activation lo plane
__device__ __nv_bfloat16 g_wh[HID * HID];   // weight hi plane (reused per GEMM)
__device__ __nv_bfloat16 g_wl[HID * HID];   // weight lo plane

// =================== baseline-PTX helpers (sm_80+ ISA only) =================
__device__ __forceinline__ uint32_t smem_u32(const void* p) {
    uint32_t a;
    asm("{ .reg .u64 t; cvta.to.shared.u64 t, %1; cvt.u32.u64 %0, t; }" : "=r"(a) : "l"(p));
    return a;
}
__device__ __forceinline__ void cpasync16(uint32_t dst, const void* src) {
    asm volatile("cp.async.cg.shared.global [%0], [%1], 16;" :: "r"(dst), "l"(src));
}
#define CP_COMMIT() asm volatile("cp.async.commit_group;" ::: "memory")
#define CP_WAIT1()  asm volatile("cp.async.wait_group 1;" ::: "memory")
#define CP_WAIT0()  asm volatile("cp.async.wait_group 0;" ::: "memory")

#define LDSM_X4(r0, r1, r2, r3, addr) \
    asm volatile("ldmatrix.sync.aligned.m8n8.x4.shared.b16 {%0,%1,%2,%3}, [%4];" \
                 : "=r"(r0), "=r"(r1), "=r"(r2), "=r"(r3) : "r"(addr))
#define LDSM_X2(r0, r1, addr) \
    asm volatile("ldmatrix.sync.aligned.m8n8.x2.shared.b16 {%0,%1}, [%2];" \
                 : "=r"(r0), "=r"(r1) : "r"(addr))

#define MMA16816(d, a, b) \
    asm volatile("mma.sync.aligned.m16n8k16.row.col.f32.bf16.bf16.f32 " \
                 "{%0,%1,%2,%3}, {%4,%5,%6,%7}, {%8,%9}, {%0,%1,%2,%3};" \
                 : "+f"((d)[0]), "+f"((d)[1]), "+f"((d)[2]), "+f"((d)[3]) \
                 : "r"((a)[0]), "r"((a)[1]), "r"((a)[2]), "r"((a)[3]), \
                   "r"((b)[0]), "r"((b)[1]))

__device__ __forceinline__ uint32_t bf2bits(__nv_bfloat162 v) {
    return *reinterpret_cast<uint32_t*>(&v);
}

// =================== fp32 -> bf16 hi/lo split ===============================
__global__ __launch_bounds__(256) void split_hi_lo(
    const float* __restrict__ in, __nv_bfloat16* __restrict__ hi,
    __nv_bfloat16* __restrict__ lo, int n4)
{
    int i = blockIdx.x * 256 + threadIdx.x;
    if (i >= n4) return;
    float4 v = reinterpret_cast<const float4*>(in)[i];
    __nv_bfloat162 h01 = __floats2bfloat162_rn(v.x, v.y);
    __nv_bfloat162 h23 = __floats2bfloat162_rn(v.z, v.w);
    float2 f01 = __bfloat1622float2(h01);
    float2 f23 = __bfloat1622float2(h23);
    __nv_bfloat162 l01 = __floats2bfloat162_rn(v.x - f01.x, v.y - f01.y);
    __nv_bfloat162 l23 = __floats2bfloat162_rn(v.z - f23.x, v.w - f23.y);
    reinterpret_cast<uint2*>(hi)[i] = make_uint2(bf2bits(h01), bf2bits(h23));
    reinterpret_cast<uint2*>(lo)[i] = make_uint2(bf2bits(l01), bf2bits(l23));
}

// =================== bf16x3 GEMM via mma.sync ===============================
// C[4096,2048] fp32 = (Ah+Al)[4096,2048] * (Bh+Bl)[2048,2048]^T
// (combos AhBh + AhBl + AlBh). CTA tile 128x128, K-tile 32 bf16.
// 2-stage cp.async pipeline; smem XOR swizzle; warp grid 2(m) x 4(n),
// warp tile 64x32 -> 4x4 frags of m16n8, 64 fp32 accum regs.

#define KTILE 32
#define NT (GK / KTILE)        // 64
#define ROWB 64                // bytes per smem row (32 bf16)
#define PLANE 8192             // 128 rows * 64B
#define STAGEB (4 * PLANE)     // Ah, Al, Bh, Bl
#define GEMM_SMEM (2 * STAGEB) // 64 KB

// swizzled byte offset within a plane: row r (0..127), 16B chunk c (0..3)
#define SWZ(r, c) ((uint32_t)((r) * ROWB + (((c) ^ (((r) >> 1) & 3)) * 16)))

__global__ __launch_bounds__(256) void gemm_bf16x3(
    const __nv_bfloat16* __restrict__ Ah, const __nv_bfloat16* __restrict__ Al,
    const __nv_bfloat16* __restrict__ Bh, const __nv_bfloat16* __restrict__ Bl,
    float* __restrict__ C)
{
    extern __shared__ char smem[];
    const uint32_t sb = smem_u32(smem);
    const int tid  = threadIdx.x;
    const int lane = tid & 31;
    const int w    = tid >> 5;
    const int bm   = blockIdx.y * 128;
    const int bn   = blockIdx.x * 128;

    // per-thread load coords: row r = tid/2, chunk pair c0 = (tid&1)*2
    const int lr  = tid >> 1;
    const int lc0 = (tid & 1) << 1;
    const __nv_bfloat16* gAh = Ah + (size_t)(bm + lr) * GK + lc0 * 8;
    const __nv_bfloat16* gAl = Al + (size_t)(bm + lr) * GK + lc0 * 8;
    const __nv_bfloat16* gBh = Bh + (size_t)(bn + lr) * GK + lc0 * 8;
    const __nv_bfloat16* gBl = Bl + (size_t)(bn + lr) * GK + lc0 * 8;
    const uint32_t s0 = SWZ(lr, lc0), s1 = SWZ(lr, lc0 + 1);

    auto load_stage = [&](int t, int st) {
        const uint32_t base = sb + st * STAGEB;
        const int ko = t * KTILE;
        cpasync16(base + 0 * PLANE + s0, gAh + ko);
        cpasync16(base + 0 * PLANE + s1, gAh + ko + 8);
        cpasync16(base + 1 * PLANE + s0, gAl + ko);
        cpasync16(base + 1 * PLANE + s1, gAl + ko + 8);
        cpasync16(base + 2 * PLANE + s0, gBh + ko);
        cpasync16(base + 2 * PLANE + s1, gBh + ko + 8);
        cpasync16(base + 3 * PLANE + s0, gBl + ko);
        cpasync16(base + 3 * PLANE + s1, gBl + ko + 8);
    };

    // warp tiling
    const int wm = w & 1;            // 2 warps over M
    const int wn = w >> 1;           // 4 warps over N
    const int m0 = wm * 64;          // within tile
    const int n0 = wn * 32;

    // ldmatrix lane-address components
    const int a_row = ((lane >> 3) & 1) * 8 + (lane & 7);  // 0..15 pattern
    const int a_ch  = (lane >> 4) & 1;                     // k chunk select
    const int bl15  = lane & 15;
    const int b_row = bl15 & 7;
    const int b_ch  = (bl15 >> 3) & 1;

    float acc[16][4];
#pragma unroll
    for (int i = 0; i < 16; i++)
#pragma unroll
        for (int j = 0; j < 4; j++) acc[i][j] = 0.f;

    load_stage(0, 0);
    CP_COMMIT();

    for (int t = 0; t < NT; t++) {
        if (t + 1 < NT) {
            load_stage(t + 1, (t + 1) & 1);
            CP_COMMIT();
            CP_WAIT1();
        } else {
            CP_WAIT0();
        }
        __syncthreads();

        const uint32_t stage = sb + (t & 1) * STAGEB;
#pragma unroll
        for (int ap = 0; ap < 2; ap++) {           // Ah then Al
            const uint32_t aBase = stage + ap * PLANE;
#pragma unroll
            for (int ks = 0; ks < 2; ks++) {       // two k16 steps
                uint32_t a[4][4];
#pragma unroll
                for (int fm = 0; fm < 4; fm++) {
                    uint32_t addr = aBase + SWZ(m0 + fm * 16 + a_row, 2 * ks + a_ch);
                    LDSM_X4(a[fm][0], a[fm][1], a[fm][2], a[fm][3], addr);
                }
                const int nB = (ap == 0) ? 2 : 1;  // Ah:{Bh,Bl}  Al:{Bh}
#pragma unroll
                for (int bp = 0; bp < nB; bp++) {
                    const uint32_t bBase = stage + (2 + bp) * PLANE;
#pragma unroll
                    for (int fn = 0; fn < 4; fn++) {
                        uint32_t b[2];
                        uint32_t addr = bBase + SWZ(n0 + fn * 8 + b_row, 2 * ks + b_ch);
                        LDSM_X2(b[0], b[1], addr);
#pragma unroll
                        for (int fm = 0; fm < 4; fm++)
                            MMA16816(acc[fm * 4 + fn], a[fm], b);
                    }
                }
            }
        }
        __syncthreads();
    }

    // epilogue: direct fp32 stores
    const int er = lane >> 2;        // 0..7
    const int ec = (lane & 3) * 2;   // 0,2,4,6
#pragma unroll
    for (int fm = 0; fm < 4; fm++) {
#pragma unroll
        for (int fn = 0; fn < 4; fn++) {
            float* p = C + (size_t)(bm + m0 + fm * 16 + er) * GN + bn + n0 + fn * 8 + ec;
            float2 d01 = {acc[fm * 4 + fn][0], acc[fm * 4 + fn][1]};
            float2 d23 = {acc[fm * 4 + fn][2], acc[fm * 4 + fn][3]};
            *reinterpret_cast<float2*>(p)            = d01;
            *reinterpret_cast<float2*>(p + 8 * GN)   = d23;
        }
    }
}

// ---------------- block-sparse attention (unchanged from R1) ----------------
#define QSTRIDE 132

__global__ __launch_bounds__(256) void attn_sparse(
    const float* __restrict__ Q, const float* __restrict__ K,
    const float* __restrict__ V, const int* __restrict__ rand_idx,
    float* __restrict__ O)
{
    extern __shared__ float smemf[];
    float* Qs  = smemf;
    float* KVs = Qs + 64 * QSTRIDE;
    float* Ssm = KVs + 64 * QSTRIDE;
    float* msm = Ssm + 64 * 65;
    float* lsm = msm + 64;
    float* csm = lsm + 64;
    __shared__ int blist[8];
    __shared__ int nblk;

    const int tid = threadIdx.x;
    const int qb  = blockIdx.x;
    const int h   = blockIdx.y;

    if (tid == 0) {
        int cand[6];
        cand[0] = qb; cand[1] = qb - 1; cand[2] = qb + 1;
        cand[3] = 0;  cand[4] = NB - 1; cand[5] = rand_idx[qb];
        int cnt = 0;
        for (int c = 0; c < 6; c++) {
            int b = cand[c];
            if (b < 0 || b >= NB) continue;
            bool dup = false;
            for (int d = 0; d < cnt; d++) if (blist[d] == b) dup = true;
            if (!dup) blist[cnt++] = b;
        }
        nblk = cnt;
    }
    if (tid < 64) { msm[tid] = -1e30f; lsm[tid] = 0.f; }

    const float* Qg = Q + (size_t)(qb * BLK) * HID + h * HD;
    for (int i = tid; i < 64 * 32; i += 256) {
        int r = i >> 5, c4 = (i & 31) << 2;
        *reinterpret_cast<float4*>(Qs + r * QSTRIDE + c4) =
            *reinterpret_cast<const float4*>(Qg + (size_t)r * HID + c4);
    }
    __syncthreads();

    const int tx = tid & 15, ty = tid >> 4;
    const int r0 = ty * 4;
    const int cS0 = tx * 4;
    const int cO0 = tx * 8;
    float oacc[4][8];
#pragma unroll
    for (int i = 0; i < 4; i++)
#pragma unroll
        for (int c = 0; c < 8; c++) oacc[i][c] = 0.f;

    for (int bi = 0; bi < nblk; bi++) {
        const int j = blist[bi];

        const float* Kg = K + (size_t)(j * BLK) * HID + h * HD;
        for (int i = tid; i < 64 * 32; i += 256) {
            int r = i >> 5, c4 = (i & 31) << 2;
            *reinterpret_cast<float4*>(KVs + r * QSTRIDE + c4) =
                *reinterpret_cast<const float4*>(Kg + (size_t)r * HID + c4);
        }
        __syncthreads();

        float s[4][4];
#pragma unroll
        for (int i = 0; i < 4; i++)
#pragma unroll
            for (int jj = 0; jj < 4; jj++) s[i][jj] = 0.f;

        for (int k = 0; k < HD; k += 4) {
            float4 q4[4], k4[4];
#pragma unroll
            for (int i = 0; i < 4; i++)
                q4[i] = *reinterpret_cast<const float4*>(Qs + (r0 + i) * QSTRIDE + k);
#pragma unroll
            for (int jj = 0; jj < 4; jj++)
                k4[jj] = *reinterpret_cast<const float4*>(KVs + (cS0 + jj) * QSTRIDE + k);
#pragma unroll
            for (int i = 0; i < 4; i++)
#pragma unroll
                for (int jj = 0; jj < 4; jj++)
                    s[i][jj] += q4[i].x * k4[jj].x + q4[i].y * k4[jj].y +
                                q4[i].z * k4[jj].z + q4[i].w * k4[jj].w;
        }
#pragma unroll
        for (int i = 0; i < 4; i++)
#pragma unroll
            for (int jj = 0; jj < 4; jj++)
                Ssm[(r0 + i) * 65 + cS0 + jj] = s[i][jj] * SCALE;
        __syncthreads();

        const float* Vg = V + (size_t)(j * BLK) * HID + h * HD;
        for (int i = tid; i < 64 * 32; i += 256) {
            int r = i >> 5, c4 = (i & 31) << 2;
            *reinterpret_cast<float4*>(KVs + r * QSTRIDE + c4) =
                *reinterpret_cast<const float4*>(Vg + (size_t)r * HID + c4);
        }
        if (tid < 64) {
            float* srow = Ssm + tid * 65;
            float m_old = msm[tid];
            float mx = m_old;
            for (int c = 0; c < 64; c++) mx = fmaxf(mx, srow[c]);
            float corr = __expf(m_old - mx);
            float sum = 0.f;
            for (int c = 0; c < 64; c++) {
                float e = __expf(srow[c] - mx);
                srow[c] = e;
                sum += e;
            }
            lsm[tid] = lsm[tid] * corr + sum;
            msm[tid] = mx;
            csm[tid] = corr;
        }
        __syncthreads();

        float cr[4];
#pragma unroll
        for (int i = 0; i < 4; i++) {
            cr[i] = csm[r0 + i];
#pragma unroll
            for (int c = 0; c < 8; c++) oacc[i][c] *= cr[i];
        }
#pragma unroll 4
        for (int kk = 0; kk < 64; kk++) {
            float4 v0 = *reinterpret_cast<const float4*>(KVs + kk * QSTRIDE + cO0);
            float4 v1 = *reinterpret_cast<const float4*>(KVs + kk * QSTRIDE + cO0 + 4);
            float p[4];
#pragma unroll
            for (int i = 0; i < 4; i++) p[i] = Ssm[(r0 + i) * 65 + kk];
#pragma unroll
            for (int i = 0; i < 4; i++) {
                oacc[i][0] = fmaf(p[i], v0.x, oacc[i][0]);
                oacc[i][1] = fmaf(p[i], v0.y, oacc[i][1]);
                oacc[i][2] = fmaf(p[i], v0.z, oacc[i][2]);
                oacc[i][3] = fmaf(p[i], v0.w, oacc[i][3]);
                oacc[i][4] = fmaf(p[i], v1.x, oacc[i][4]);
                oacc[i][5] = fmaf(p[i], v1.y, oacc[i][5]);
                oacc[i][6] = fmaf(p[i], v1.z, oacc[i][6]);
                oacc[i][7] = fmaf(p[i], v1.w, oacc[i][7]);
            }
        }
        __syncthreads();
    }

    float* Og = O + (size_t)(qb * BLK) * HID + h * HD;
#pragma unroll
    for (int i = 0; i < 4; i++) {
        float inv = 1.f / lsm[r0 + i];
        float4 o0 = {oacc[i][0] * inv, oacc[i][1] * inv, oacc[i][2] * inv, oacc[i][3] * inv};
        float4 o1 = {oacc[i][4] * inv, oacc[i][5] * inv, oacc[i][6] * inv, oacc[i][7] * inv};
        *reinterpret_cast<float4*>(Og + (size_t)(r0 + i) * HID + cO0)     = o0;
        *reinterpret_cast<float4*>(Og + (size_t)(r0 + i) * HID + cO0 + 4) = o1;
    }
}

// ---------------- launch -----------------------------------------------------
#define ATTN_SMEM_BYTES ((64 * QSTRIDE * 2 + 64 * 65 + 3 * 64) * (int)sizeof(float))

extern "C" void kernel_launch(void* const* d_in, const int* in_sizes, int n_in,
                              void* d_out, int out_size)
{
    const float* x    = (const float*)d_in[0];
    const int*   ridx = (const int*)d_in[1];
    const float* Wq   = (const float*)d_in[2];
    const float* Wk   = (const float*)d_in[3];
    const float* Wv   = (const float*)d_in[4];
    const float* Wo   = (const float*)d_in[5];
    float* out = (float*)d_out;

    float *q, *k, *v, *attn;
    __nv_bfloat16 *ah, *al, *wh, *wl;
    cudaGetSymbolAddress((void**)&q,    g_q);
    cudaGetSymbolAddress((void**)&k,    g_k);
    cudaGetSymbolAddress((void**)&v,    g_v);
    cudaGetSymbolAddress((void**)&attn, g_attn);
    cudaGetSymbolAddress((void**)&ah,   g_ah);
    cudaGetSymbolAddress((void**)&al,   g_al);
    cudaGetSymbolAddress((void**)&wh,   g_wh);
    cudaGetSymbolAddress((void**)&wl,   g_wl);

    cudaFuncSetAttribute(gemm_bf16x3,
                         cudaFuncAttributeMaxDynamicSharedMemorySize, GEMM_SMEM);
    cudaFuncSetAttribute(attn_sparse,
                         cudaFuncAttributeMaxDynamicSharedMemorySize, ATTN_SMEM_BYTES);

    const int nact4 = SEQ * HID / 4;   // 2M float4
    const int nw4   = HID * HID / 4;   // 1M float4
    dim3 ggrid(GN / 128, GM / 128);    // (16, 32)

    split_hi_lo<<<(nact4 + 255) / 256, 256>>>(x, ah, al, nact4);

    split_hi_lo<<<(nw4 + 255) / 256, 256>>>(Wq, wh, wl, nw4);
    gemm_bf16x3<<<ggrid, 256, GEMM_SMEM>>>(ah, al, wh, wl, q);

    split_hi_lo<<<(nw4 + 255) / 256, 256>>>(Wk, wh, wl, nw4);
    gemm_bf16x3<<<ggrid, 256, GEMM_SMEM>>>(ah, al, wh, wl, k);

    split_hi_lo<<<(nw4 + 255) / 256, 256>>>(Wv, wh, wl, nw4);
    gemm_bf16x3<<<ggrid, 256, GEMM_SMEM>>>(ah, al, wh, wl, v);

    attn_sparse<<<dim3(NB, HEADS), 256, ATTN_SMEM_BYTES>>>(q, k, v, ridx, attn);

    split_hi_lo<<<(nact4 + 255) / 256, 256>>>(attn, ah, al, nact4);
    split_hi_lo<<<(nw4 + 255) / 256, 256>>>(Wo, wh, wl, nw4);
    gemm_bf16x3<<<ggrid, 256, GEMM_SMEM>>>(ah, al, wh, wl, out);
}

// round 4
// speedup vs baseline: 3.1344x; 1.6395x over previous
#include <cuda_runtime.h>
#include <cuda_bf16.h>
#include <cstdint>
#include <cstddef>

#define SEQ    4096
#define HID    2048
#define HEADS  16
#define HD     128
#define NB     64
#define SCALE  0.08838834764831845f   // 1/sqrt(128)

#define GM 4096
#define GN 2048
#define GK 2048

// ---------------- scratch planes (device globals; no allocation allowed) ----
__device__ __nv_bfloat16 g_ah[SEQ * HID], g_al[SEQ * HID];   // activations
__device__ __nv_bfloat16 g_qh[SEQ * HID], g_ql[SEQ * HID];
__device__ __nv_bfloat16 g_kh[SEQ * HID], g_kl[SEQ * HID];
__device__ __nv_bfloat16 g_vh[SEQ * HID], g_vl[SEQ * HID];
__device__ __nv_bfloat16 g_oh[SEQ * HID], g_ol[SEQ * HID];   // attn output
__device__ __nv_bfloat16 g_wqh[HID * HID], g_wql[HID * HID];
__device__ __nv_bfloat16 g_wkh[HID * HID], g_wkl[HID * HID];
__device__ __nv_bfloat16 g_wvh[HID * HID], g_wvl[HID * HID];
__device__ __nv_bfloat16 g_woh[HID * HID], g_wol[HID * HID];

// =================== baseline-PTX helpers (sm_80+ ISA only) =================
__device__ __forceinline__ uint32_t smem_u32(const void* p) {
    uint32_t a;
    asm("{ .reg .u64 t; cvta.to.shared.u64 t, %1; cvt.u32.u64 %0, t; }" : "=r"(a) : "l"(p));
    return a;
}
__device__ __forceinline__ void cpasync16(uint32_t dst, const void* src) {
    asm volatile("cp.async.cg.shared.global [%0], [%1], 16;" :: "r"(dst), "l"(src));
}
#define CP_COMMIT() asm volatile("cp.async.commit_group;" ::: "memory")
#define CP_WAIT1()  asm volatile("cp.async.wait_group 1;" ::: "memory")
#define CP_WAIT0()  asm volatile("cp.async.wait_group 0;" ::: "memory")

#define LDSM_X4(r0, r1, r2, r3, addr) \
    asm volatile("ldmatrix.sync.aligned.m8n8.x4.shared.b16 {%0,%1,%2,%3}, [%4];" \
                 : "=r"(r0), "=r"(r1), "=r"(r2), "=r"(r3) : "r"(addr))
#define LDSM_X2(r0, r1, addr) \
    asm volatile("ldmatrix.sync.aligned.m8n8.x2.shared.b16 {%0,%1}, [%2];" \
                 : "=r"(r0), "=r"(r1) : "r"(addr))
#define LDSM_X4_T(r0, r1, r2, r3, addr) \
    asm volatile("ldmatrix.sync.aligned.m8n8.x4.trans.shared.b16 {%0,%1,%2,%3}, [%4];" \
                 : "=r"(r0), "=r"(r1), "=r"(r2), "=r"(r3) : "r"(addr))

__device__ __forceinline__ void mma16816(float* d, const uint32_t* a, const uint32_t* b) {
    asm volatile("mma.sync.aligned.m16n8k16.row.col.f32.bf16.bf16.f32 "
                 "{%0,%1,%2,%3}, {%4,%5,%6,%7}, {%8,%9}, {%0,%1,%2,%3};"
                 : "+f"(d[0]), "+f"(d[1]), "+f"(d[2]), "+f"(d[3])
                 : "r"(a[0]), "r"(a[1]), "r"(a[2]), "r"(a[3]), "r"(b[0]), "r"(b[1]));
}

__device__ __forceinline__ uint32_t bf2bits(__nv_bfloat162 v) {
    return *reinterpret_cast<uint32_t*>(&v);
}
__device__ __forceinline__ void pack_hilo(float x, float y, uint32_t& hi, uint32_t& lo) {
    __nv_bfloat162 h = __floats2bfloat162_rn(x, y);
    float2 f = __bfloat1622float2(h);
    __nv_bfloat162 l = __floats2bfloat162_rn(x - f.x, y - f.y);
    hi = bf2bits(h); lo = bf2bits(l);
}

// =================== fp32 -> bf16 hi/lo split ===============================
__global__ __launch_bounds__(256) void split_hi_lo(
    const float* __restrict__ in, __nv_bfloat16* __restrict__ hi,
    __nv_bfloat16* __restrict__ lo, int n4)
{
    int i = blockIdx.x * 256 + threadIdx.x;
    if (i >= n4) return;
    float4 v = reinterpret_cast<const float4*>(in)[i];
    uint32_t h01, l01, h23, l23;
    pack_hilo(v.x, v.y, h01, l01);
    pack_hilo(v.z, v.w, h23, l23);
    reinterpret_cast<uint2*>(hi)[i] = make_uint2(h01, h23);
    reinterpret_cast<uint2*>(lo)[i] = make_uint2(l01, l23);
}

// =================== bf16x3 GEMM core (mma.sync) ============================
#define KTILE 32
#define NT (GK / KTILE)
#define ROWB 64
#define PLANE 8192
#define STAGEB (4 * PLANE)
#define GEMM_SMEM (2 * STAGEB)
#define SWZ(r, c) ((uint32_t)((r) * ROWB + (((c) ^ (((r) >> 1) & 3)) * 16)))

template<bool SPLIT_OUT>
__device__ __forceinline__ void gemm_core(
    const __nv_bfloat16* __restrict__ Ah, const __nv_bfloat16* __restrict__ Al,
    const __nv_bfloat16* __restrict__ Bh, const __nv_bfloat16* __restrict__ Bl,
    float* __restrict__ C, __nv_bfloat16* __restrict__ Ch, __nv_bfloat16* __restrict__ Cl)
{
    extern __shared__ char smem[];
    const uint32_t sb = smem_u32(smem);
    const int tid  = threadIdx.x;
    const int lane = tid & 31;
    const int w    = tid >> 5;
    const int bm   = blockIdx.y * 128;
    const int bn   = blockIdx.x * 128;

    const int lr  = tid >> 1;
    const int lc0 = (tid & 1) << 1;
    const __nv_bfloat16* gAh = Ah + (size_t)(bm + lr) * GK + lc0 * 8;
    const __nv_bfloat16* gAl = Al + (size_t)(bm + lr) * GK + lc0 * 8;
    const __nv_bfloat16* gBh = Bh + (size_t)(bn + lr) * GK + lc0 * 8;
    const __nv_bfloat16* gBl = Bl + (size_t)(bn + lr) * GK + lc0 * 8;
    const uint32_t s0 = SWZ(lr, lc0), s1 = SWZ(lr, lc0 + 1);

    auto load_stage = [&](int t, int st) {
        const uint32_t base = sb + st * STAGEB;
        const int ko = t * KTILE;
        cpasync16(base + 0 * PLANE + s0, gAh + ko);
        cpasync16(base + 0 * PLANE + s1, gAh + ko + 8);
        cpasync16(base + 1 * PLANE + s0, gAl + ko);
        cpasync16(base + 1 * PLANE + s1, gAl + ko + 8);
        cpasync16(base + 2 * PLANE + s0, gBh + ko);
        cpasync16(base + 2 * PLANE + s1, gBh + ko + 8);
        cpasync16(base + 3 * PLANE + s0, gBl + ko);
        cpasync16(base + 3 * PLANE + s1, gBl + ko + 8);
    };

    const int wm = w & 1;
    const int wn = w >> 1;
    const int m0 = wm * 64;
    const int n0 = wn * 32;

    const int a_row = ((lane >> 3) & 1) * 8 + (lane & 7);
    const int a_ch  = (lane >> 4) & 1;
    const int bl15  = lane & 15;
    const int b_row = bl15 & 7;
    const int b_ch  = (bl15 >> 3) & 1;

    float acc[16][4];
#pragma unroll
    for (int i = 0; i < 16; i++)
#pragma unroll
        for (int j = 0; j < 4; j++) acc[i][j] = 0.f;

    load_stage(0, 0);
    CP_COMMIT();

    for (int t = 0; t < NT; t++) {
        if (t + 1 < NT) {
            load_stage(t + 1, (t + 1) & 1);
            CP_COMMIT();
            CP_WAIT1();
        } else {
            CP_WAIT0();
        }
        __syncthreads();

        const uint32_t stage = sb + (t & 1) * STAGEB;
#pragma unroll
        for (int ap = 0; ap < 2; ap++) {
            const uint32_t aBase = stage + ap * PLANE;
#pragma unroll
            for (int ks = 0; ks < 2; ks++) {
                uint32_t a[4][4];
#pragma unroll
                for (int fm = 0; fm < 4; fm++) {
                    uint32_t addr = aBase + SWZ(m0 + fm * 16 + a_row, 2 * ks + a_ch);
                    LDSM_X4(a[fm][0], a[fm][1], a[fm][2], a[fm][3], addr);
                }
                const int nB = (ap == 0) ? 2 : 1;
#pragma unroll
                for (int bp = 0; bp < nB; bp++) {
                    const uint32_t bBase = stage + (2 + bp) * PLANE;
#pragma unroll
                    for (int fn = 0; fn < 4; fn++) {
                        uint32_t b[2];
                        uint32_t addr = bBase + SWZ(n0 + fn * 8 + b_row, 2 * ks + b_ch);
                        LDSM_X2(b[0], b[1], addr);
#pragma unroll
                        for (int fm = 0; fm < 4; fm++)
                            mma16816(acc[fm * 4 + fn], a[fm], b);
                    }
                }
            }
        }
        __syncthreads();
    }

    const int er = lane >> 2;
    const int ec = (lane & 3) * 2;
#pragma unroll
    for (int fm = 0; fm < 4; fm++) {
#pragma unroll
        for (int fn = 0; fn < 4; fn++) {
            const size_t r0 = (size_t)(bm + m0 + fm * 16 + er) * GN + bn + n0 + fn * 8 + ec;
            const size_t r1 = r0 + (size_t)8 * GN;
            float* ac = acc[fm * 4 + fn];
            if (SPLIT_OUT) {
                uint32_t h0, l0, h1, l1;
                pack_hilo(ac[0], ac[1], h0, l0);
                pack_hilo(ac[2], ac[3], h1, l1);
                *reinterpret_cast<uint32_t*>(Ch + r0) = h0;
                *reinterpret_cast<uint32_t*>(Cl + r0) = l0;
                *reinterpret_cast<uint32_t*>(Ch + r1) = h1;
                *reinterpret_cast<uint32_t*>(Cl + r1) = l1;
            } else {
                *reinterpret_cast<float2*>(C + r0) = make_float2(ac[0], ac[1]);
                *reinterpret_cast<float2*>(C + r1) = make_float2(ac[2], ac[3]);
            }
        }
    }
}

// fused QKV GEMM: blockIdx.z selects weight planes + output planes
__global__ __launch_bounds__(256) void gemm_qkv()
{
    const int z = blockIdx.z;
    const __nv_bfloat16* Bh = (z == 0) ? g_wqh : (z == 1) ? g_wkh : g_wvh;
    const __nv_bfloat16* Bl = (z == 0) ? g_wql : (z == 1) ? g_wkl : g_wvl;
    __nv_bfloat16* Ch = (z == 0) ? g_qh : (z == 1) ? g_kh : g_vh;
    __nv_bfloat16* Cl = (z == 0) ? g_ql : (z == 1) ? g_kl : g_vl;
    gemm_core<true>(g_ah, g_al, Bh, Bl, nullptr, Ch, Cl);
}

__global__ __launch_bounds__(256) void gemm_out(float* __restrict__ C)
{
    gemm_core<false>(g_oh, g_ol, g_woh, g_wol, C, nullptr, nullptr);
}

// =================== flash-style sparse attention (mma.sync, bf16x3) ========
// One CTA (128 thr, 4 warps) per (q-block, head). S and O in mma fragments;
// online softmax in registers via shuffles. K/V prefetch via cp.async.
// smem: Qh Ql (16KB ea) | K buf hi/lo | V buf hi/lo  => 96KB.
#define SA(r, c) ((uint32_t)((r) * 256 + (((c) ^ ((r) & 7)) * 16)))
#define ATTN_SMEM (6 * 16384)

__global__ __launch_bounds__(128) void attn_mma(const int* __restrict__ rand_idx)
{
    extern __shared__ char smem[];
    const uint32_t sb = smem_u32(smem);
    const int tid  = threadIdx.x;
    const int lane = tid & 31;
    const int w    = tid >> 5;
    const int qb   = blockIdx.x;
    const int h    = blockIdx.y;

    // candidate kv-block list (identical in every thread)
    int blist[6]; int nblk = 0;
    {
        int cand[6] = {qb, qb - 1, qb + 1, 0, NB - 1, rand_idx[qb]};
#pragma unroll
        for (int c = 0; c < 6; c++) {
            int b = cand[c];
            if (b < 0 || b >= NB) continue;
            bool dup = false;
            for (int d = 0; d < nblk; d++) dup |= (blist[d] == b);
            if (!dup) blist[nblk++] = b;
        }
    }

    const uint32_t QH = sb,             QL = sb + 16384;
    const uint32_t KH = sb + 2 * 16384, KL = sb + 3 * 16384;
    const uint32_t VH = sb + 4 * 16384, VL = sb + 5 * 16384;

    auto load_tile = [&](uint32_t dh, uint32_t dl,
                         const __nv_bfloat16* gh, const __nv_bfloat16* gl, int j) {
        const __nv_bfloat16* sh = gh + (size_t)(j * 64) * HID + h * HD;
        const __nv_bfloat16* sl = gl + (size_t)(j * 64) * HID + h * HD;
#pragma unroll
        for (int t = 0; t < 8; t++) {
            int cid = tid + t * 128;          // 0..1023
            int r = cid >> 4, c = cid & 15;
            cpasync16(dh + SA(r, c), sh + (size_t)r * HID + c * 8);
            cpasync16(dl + SA(r, c), sl + (size_t)r * HID + c * 8);
        }
    };

    // prologue: Q + K[0] in one group
    load_tile(QH, QL, g_qh, g_ql, qb);
    load_tile(KH, KL, g_kh, g_kl, blist[0]);
    CP_COMMIT();

    // fragment geometry
    const int aRow  = w * 16 + (lane & 7) + ((lane >> 3) & 1) * 8;
    const int aCh   = (lane >> 4) & 1;
    const int bTile = lane >> 3;

    float o[16][4];
#pragma unroll
    for (int i = 0; i < 16; i++)
#pragma unroll
        for (int j = 0; j < 4; j++) o[i][j] = 0.f;
    float m0 = -1e30f, m1 = -1e30f, l0 = 0.f, l1 = 0.f;

    for (int bi = 0; bi < nblk; bi++) {
        CP_WAIT0();
        __syncthreads();

        // prefetch V[bi]
        load_tile(VH, VL, g_vh, g_vl, blist[bi]);
        CP_COMMIT();

        // ---- S = (Qh+Ql)(Kh+Kl)^T, fp32 accum, 3 combos ----
        float s[8][4];
#pragma unroll
        for (int i = 0; i < 8; i++)
#pragma unroll
            for (int j = 0; j < 4; j++) s[i][j] = 0.f;

#pragma unroll
        for (int ks = 0; ks < 8; ks++) {
            uint32_t aqh[4], aql[4];
            LDSM_X4(aqh[0], aqh[1], aqh[2], aqh[3], QH + SA(aRow, 2 * ks + aCh));
            LDSM_X4(aql[0], aql[1], aql[2], aql[3], QL + SA(aRow, 2 * ks + aCh));
#pragma unroll
            for (int fn = 0; fn < 8; fn += 2) {
                const int br = (fn + (bTile >> 1)) * 8 + (lane & 7);
                const int bc = 2 * ks + (bTile & 1);
                uint32_t kh4[4], kl4[4];
                LDSM_X4(kh4[0], kh4[1], kh4[2], kh4[3], KH + SA(br, bc));
                LDSM_X4(kl4[0], kl4[1], kl4[2], kl4[3], KL + SA(br, bc));
                mma16816(s[fn],     aqh, kh4 + 0);
                mma16816(s[fn],     aqh, kl4 + 0);
                mma16816(s[fn],     aql, kh4 + 0);
                mma16816(s[fn + 1], aqh, kh4 + 2);
                mma16816(s[fn + 1], aqh, kl4 + 2);
                mma16816(s[fn + 1], aql, kh4 + 2);
            }
        }
        __syncthreads();               // all warps done reading K buffer

        if (bi + 1 < nblk) {           // prefetch K[bi+1] into K buffer
            load_tile(KH, KL, g_kh, g_kl, blist[bi + 1]);
            CP_COMMIT();
        }

        // ---- online softmax (register domain) ----
        float rmax0 = -1e30f, rmax1 = -1e30f;
#pragma unroll
        for (int fn = 0; fn < 8; fn++) {
            rmax0 = fmaxf(rmax0, fmaxf(s[fn][0], s[fn][1]));
            rmax1 = fmaxf(rmax1, fmaxf(s[fn][2], s[fn][3]));
        }
        rmax0 = fmaxf(rmax0, __shfl_xor_sync(0xffffffffu, rmax0, 1));
        rmax0 = fmaxf(rmax0, __shfl_xor_sync(0xffffffffu, rmax0, 2));
        rmax1 = fmaxf(rmax1, __shfl_xor_sync(0xffffffffu, rmax1, 1));
        rmax1 = fmaxf(rmax1, __shfl_xor_sync(0xffffffffu, rmax1, 2));
        const float mn0 = fmaxf(m0, rmax0 * SCALE);
        const float mn1 = fmaxf(m1, rmax1 * SCALE);
        const float corr0 = __expf(m0 - mn0);
        const float corr1 = __expf(m1 - mn1);
        float sum0 = 0.f, sum1 = 0.f;
#pragma unroll
        for (int fn = 0; fn < 8; fn++) {
            s[fn][0] = __expf(fmaf(s[fn][0], SCALE, -mn0));
            s[fn][1] = __expf(fmaf(s[fn][1], SCALE, -mn0));
            s[fn][2] = __expf(fmaf(s[fn][2], SCALE, -mn1));
            s[fn][3] = __expf(fmaf(s[fn][3], SCALE, -mn1));
            sum0 += s[fn][0] + s[fn][1];
            sum1 += s[fn][2] + s[fn][3];
        }
        sum0 += __shfl_xor_sync(0xffffffffu, sum0, 1);
        sum0 += __shfl_xor_sync(0xffffffffu, sum0, 2);
        sum1 += __shfl_xor_sync(0xffffffffu, sum1, 1);
        sum1 += __shfl_xor_sync(0xffffffffu, sum1, 2);
        l0 = l0 * corr0 + sum0; m0 = mn0;
        l1 = l1 * corr1 + sum1; m1 = mn1;

#pragma unroll
        for (int fd = 0; fd < 16; fd++) {
            o[fd][0] *= corr0; o[fd][1] *= corr0;
            o[fd][2] *= corr1; o[fd][3] *= corr1;
        }

        // pack P -> hi/lo A-fragments (4 ksteps of 16 keys)
        uint32_t ph[4][4], pl[4][4];
#pragma unroll
        for (int ks2 = 0; ks2 < 4; ks2++) {
            const int j0 = 2 * ks2, j1 = j0 + 1;
            pack_hilo(s[j0][0], s[j0][1], ph[ks2][0], pl[ks2][0]);
            pack_hilo(s[j0][2], s[j0][3], ph[ks2][1], pl[ks2][1]);
            pack_hilo(s[j1][0], s[j1][1], ph[ks2][2], pl[ks2][2]);
            pack_hilo(s[j1][2], s[j1][3], ph[ks2][3], pl[ks2][3]);
        }

        // wait V (allow pending K[bi+1])
        if (bi + 1 < nblk) CP_WAIT1(); else CP_WAIT0();
        __syncthreads();

        // ---- O += (Ph+Pl)(Vh+Vl), 3 combos; V via ldmatrix.trans ----
#pragma unroll
        for (int ks2 = 0; ks2 < 4; ks2++) {
#pragma unroll
            for (int fd = 0; fd < 16; fd += 2) {
                const int vr = ks2 * 16 + (bTile & 1) * 8 + (lane & 7);
                const int vc = fd + (bTile >> 1);
                uint32_t vh4[4], vl4[4];
                LDSM_X4_T(vh4[0], vh4[1], vh4[2], vh4[3], VH + SA(vr, vc));
                LDSM_X4_T(vl4[0], vl4[1], vl4[2], vl4[3], VL + SA(vr, vc));
                mma16816(o[fd],     ph[ks2], vh4 + 0);
                mma16816(o[fd],     ph[ks2], vl4 + 0);
                mma16816(o[fd],     pl[ks2], vh4 + 0);
                mma16816(o[fd + 1], ph[ks2], vh4 + 2);
                mma16816(o[fd + 1], ph[ks2], vl4 + 2);
                mma16816(o[fd + 1], pl[ks2], vh4 + 2);
            }
        }
    }

    // ---- epilogue: O /= l, write hi/lo planes ----
    const float inv0 = 1.f / l0;
    const float inv1 = 1.f / l1;
    const int er = lane >> 2;
    const int ec = (lane & 3) * 2;
    const size_t row0 = (size_t)(qb * 64 + w * 16 + er) * HID;
    const size_t row1 = row0 + (size_t)8 * HID;
#pragma unroll
    for (int fd = 0; fd < 16; fd++) {
        const int col = h * HD + fd * 8 + ec;
        uint32_t h0, lo0, h1, lo1;
        pack_hilo(o[fd][0] * inv0, o[fd][1] * inv0, h0, lo0);
        pack_hilo(o[fd][2] * inv1, o[fd][3] * inv1, h1, lo1);
        *reinterpret_cast<uint32_t*>(g_oh + row0 + col) = h0;
        *reinterpret_cast<uint32_t*>(g_ol + row0 + col) = lo0;
        *reinterpret_cast<uint32_t*>(g_oh + row1 + col) = h1;
        *reinterpret_cast<uint32_t*>(g_ol + row1 + col) = lo1;
    }
}

// ---------------- launch -----------------------------------------------------
extern "C" void kernel_launch(void* const* d_in, const int* in_sizes, int n_in,
                              void* d_out, int out_size)
{
    const float* x    = (const float*)d_in[0];
    const int*   ridx = (const int*)d_in[1];
    const float* Wq   = (const float*)d_in[2];
    const float* Wk   = (const float*)d_in[3];
    const float* Wv   = (const float*)d_in[4];
    const float* Wo   = (const float*)d_in[5];
    float* out = (float*)d_out;

    __nv_bfloat16 *ah, *al, *wqh, *wql, *wkh, *wkl, *wvh, *wvl, *woh, *wol;
    cudaGetSymbolAddress((void**)&ah,  g_ah);
    cudaGetSymbolAddress((void**)&al,  g_al);
    cudaGetSymbolAddress((void**)&wqh, g_wqh);
    cudaGetSymbolAddress((void**)&wql, g_wql);
    cudaGetSymbolAddress((void**)&wkh, g_wkh);
    cudaGetSymbolAddress((void**)&wkl, g_wkl);
    cudaGetSymbolAddress((void**)&wvh, g_wvh);
    cudaGetSymbolAddress((void**)&wvl, g_wvl);
    cudaGetSymbolAddress((void**)&woh, g_woh);
    cudaGetSymbolAddress((void**)&wol, g_wol);

    cudaFuncSetAttribute(gemm_qkv, cudaFuncAttributeMaxDynamicSharedMemorySize, GEMM_SMEM);
    cudaFuncSetAttribute(gemm_out, cudaFuncAttributeMaxDynamicSharedMemorySize, GEMM_SMEM);
    cudaFuncSetAttribute(attn_mma, cudaFuncAttributeMaxDynamicSharedMemorySize, ATTN_SMEM);

    const int nact4 = SEQ * HID / 4;
    const int nw4   = HID * HID / 4;

    split_hi_lo<<<(nact4 + 255) / 256, 256>>>(x,  ah,  al,  nact4);
    split_hi_lo<<<(nw4 + 255) / 256, 256>>>(Wq, wqh, wql, nw4);
    split_hi_lo<<<(nw4 + 255) / 256, 256>>>(Wk, wkh, wkl, nw4);
    split_hi_lo<<<(nw4 + 255) / 256, 256>>>(Wv, wvh, wvl, nw4);
    split_hi_lo<<<(nw4 + 255) / 256, 256>>>(Wo, woh, wol, nw4);

    gemm_qkv<<<dim3(GN / 128, GM / 128, 3), 256, GEMM_SMEM>>>();

    attn_mma<<<dim3(NB, HEADS), 128, ATTN_SMEM>>>(ridx);

    gemm_out<<<dim3(GN / 128, GM / 128, 1), 256, GEMM_SMEM>>>(out);
}